// round 8
// baseline (speedup 1.0000x reference)
#include <cuda_runtime.h>
#include <cuda_bf16.h>

#define Bdim 64
#define Cdim 64
#define Tdim 128
#define Vdim 25
#define Rdim 8
#define TSdim 9
#define OUTdim 64
#define VV (Vdim*Vdim)          // 625
#define TV (Tdim*Vdim)          // 3200
#define XSTR 136                // T + TS-1 = 136 padded row
#define WKSTR 26                // Wks row stride (25 + 1 pad for 8B-aligned pairs)

// scratch (device globals: no runtime allocation allowed)
__device__ float g_m[Bdim * Cdim * Vdim];                 // 0.41 MB  (time-mean)
__device__ float g_rel[Bdim * Rdim * VV];                 // 1.28 MB
__device__ float g_z[(size_t)Bdim * Cdim * Tdim * Vdim];  // 52.4 MB

// ---- f32x2 helpers (sm_103a packed FFMA path) ------------------------------
#define PACK_F32X2(out, lo, hi)                                        \
    asm("mov.b64 %0, {%1, %2};"                                        \
        : "=l"(out) : "r"(__float_as_uint(lo)), "r"(__float_as_uint(hi)))

#define UNPACK_F32X2(lo, hi, in)                                       \
    do { unsigned _ulo, _uhi;                                          \
         asm("mov.b64 {%0, %1}, %2;" : "=r"(_ulo), "=r"(_uhi) : "l"(in)); \
         lo = __uint_as_float(_ulo); hi = __uint_as_float(_uhi); } while (0)

#define FMA_F32X2(acc, a, b)                                           \
    asm("fma.rn.f32x2 %0, %1, %2, %0;" : "+l"(acc) : "l"(a), "l"(b))

// ---------------------------------------------------------------------------
// kA1: coalesced time-mean.  One block per (b,c): stage the (T,V) plane in
// smem via float4, reduce over t.   m[b,c,v] = mean_t x[b,c,t,v]
// ---------------------------------------------------------------------------
__global__ __launch_bounds__(128) void kA1(const float* __restrict__ x) {
    const int c = blockIdx.x, b = blockIdx.y;
    const int tid = threadIdx.x;
    __shared__ __align__(16) float pl[Tdim * Vdim];   // 12.8 KB
    __shared__ float part[100];

    const float4* src = reinterpret_cast<const float4*>(
        x + ((size_t)b * Cdim + c) * TV);
    float4* dst = reinterpret_cast<float4*>(pl);
    for (int i = tid; i < TV / 4; i += 128) dst[i] = src[i];
    __syncthreads();

    if (tid < 100) {
        const int v = tid % Vdim, q = tid / Vdim;   // q = quarter of t-range
        float s = 0.f;
#pragma unroll 8
        for (int j = 0; j < 32; j++) s += pl[(q * 32 + j) * Vdim + v];
        part[tid] = s;
    }
    __syncthreads();
    if (tid < Vdim) {
        float s = part[tid] + part[25 + tid] + part[50 + tid] + part[75 + tid];
        g_m[((size_t)b * Cdim + c) * Vdim + tid] = s * (1.0f / Tdim);
    }
}

// ---------------------------------------------------------------------------
// kA2: per-batch projections + tanh relation (tiny).
// ---------------------------------------------------------------------------
__global__ __launch_bounds__(256) void kA2(const float* __restrict__ W1,
                                           const float* __restrict__ b1,
                                           const float* __restrict__ W2,
                                           const float* __restrict__ b2) {
    const int b = blockIdx.x;
    const int tid = threadIdx.x;
    __shared__ float W1s[Rdim * Cdim], W2s[Rdim * Cdim];
    __shared__ float ms[Cdim * Vdim];
    __shared__ float x1s[Rdim * Vdim], x2s[Rdim * Vdim];

    for (int i = tid; i < Rdim * Cdim; i += 256) {
        W1s[i] = W1[i];
        W2s[i] = W2[i];
    }
    const float* mb = g_m + (size_t)b * Cdim * Vdim;
    for (int i = tid; i < Cdim * Vdim; i += 256) ms[i] = mb[i];
    __syncthreads();

    for (int item = tid; item < 2 * Rdim * Vdim; item += 256) {
        int which = item / (Rdim * Vdim);
        int rv = item % (Rdim * Vdim);
        int r = rv / Vdim, v = rv % Vdim;
        const float* Ws = which ? W2s : W1s;
        float s = which ? b2[r] : b1[r];
#pragma unroll
        for (int c = 0; c < Cdim; c++) s += Ws[r * Cdim + c] * ms[c * Vdim + v];
        if (which) x2s[rv] = s; else x1s[rv] = s;
    }
    __syncthreads();

    float* relb = g_rel + (size_t)b * Rdim * VV;
    for (int item = tid; item < Rdim * VV; item += 256) {
        int r = item / VV;
        int rem = item % VV;
        int i = rem / Vdim, j = rem % Vdim;
        relb[item] = tanhf(x1s[r * Vdim + i] - x2s[r * Vdim + j]);
    }
}

// ---------------------------------------------------------------------------
// kB: per-(b,c) fused dynamic-tap conv, packed f32x2 over the i dimension.
//   Wk[k][v][i] = b4[c*TS+k] + A[v,i] + sum_r W4[c*TS+k,r]*rel[b,r,v,i]
//   z[t,i]      = sum_{v,k} xs[v][t+k] * Wk[k][v][i]
// Thread = (tg, ip): 8 t-values x 2 adjacent i-values; 16x13 = 208 workers.
// Wk pairs (i0,i0+1) come straight from smem as LDS.64 (row stride 26 keeps
// every pair 8B-aligned; pad column 25 is zeroed). x values are broadcast
// scalars, duplicated into both halves once per v (16 movs / 72 FFMA2).
// ---------------------------------------------------------------------------
__global__ __launch_bounds__(224) void kB(const float* __restrict__ x,
                                          const float* __restrict__ A,
                                          const float* __restrict__ W4,
                                          const float* __restrict__ b4) {
    const int c = blockIdx.x;
    const int b = blockIdx.y;
    const int tid = threadIdx.x;

    __shared__ __align__(16) float Wks[TSdim * Vdim * WKSTR]; // 23.4 KB
    __shared__ __align__(16) float xs[Vdim * XSTR];           // 13.6 KB

    // build Wk (A read straight from L2; it's shared by all 4096 blocks)
    const float* relb = g_rel + (size_t)b * Rdim * VV;
    for (int item = tid; item < TSdim * VV; item += 224) {
        int k = item / VV, vi = item % VV;
        int v = vi / Vdim, i = vi % Vdim;
        const float* w4row = W4 + (size_t)(c * TSdim + k) * Rdim;
        float s = b4[c * TSdim + k] + A[vi];
#pragma unroll
        for (int r = 0; r < Rdim; r++) s += w4row[r] * relb[r * VV + vi];
        Wks[(k * Vdim + v) * WKSTR + i] = s;
    }
    for (int item = tid; item < TSdim * Vdim; item += 224)
        Wks[item * WKSTR + Vdim] = 0.f;   // zero the pad column

    // stage x tile: xs[v][0..7] = 0 (causal pad), xs[v][8+t] = x[b,c,t,v]
    for (int i = tid; i < Vdim * 8; i += 224)
        xs[(i / 8) * XSTR + (i % 8)] = 0.f;
    const float* xbc = x + ((size_t)b * Cdim + c) * TV;
    for (int item = tid; item < TV; item += 224) {
        int t = item / Vdim, v = item % Vdim;
        xs[v * XSTR + 8 + t] = xbc[item];
    }
    __syncthreads();

    if (tid < 16 * 13) {
        const int tg = tid / 13;            // 0..15  -> t0 = 8*tg
        const int ip = tid % 13;            // 0..12  -> i0 = 2*ip
        const int i0 = 2 * ip;
        const int t0 = tg * 8;

        unsigned long long acc[8];
#pragma unroll
        for (int tt = 0; tt < 8; tt++) acc[tt] = 0ull;

#pragma unroll 1
        for (int v = 0; v < Vdim; v++) {
            float xv[16];
            const float4* xp4 = reinterpret_cast<const float4*>(&xs[v * XSTR + t0]);
#pragma unroll
            for (int q = 0; q < 4; q++) {
                float4 f = xp4[q];
                xv[4 * q + 0] = f.x; xv[4 * q + 1] = f.y;
                xv[4 * q + 2] = f.z; xv[4 * q + 3] = f.w;
            }
            unsigned long long xd[16];
#pragma unroll
            for (int j = 0; j < 16; j++) PACK_F32X2(xd[j], xv[j], xv[j]);

            const float* wkbase = &Wks[v * WKSTR + i0];
#pragma unroll
            for (int k = 0; k < TSdim; k++) {
                unsigned long long wp =
                    *reinterpret_cast<const unsigned long long*>(
                        wkbase + (size_t)k * Vdim * WKSTR);
#pragma unroll
                for (int tt = 0; tt < 8; tt++) FMA_F32X2(acc[tt], xd[tt + k], wp);
            }
        }

        float* zbc = g_z + ((size_t)b * Cdim + c) * TV;
#pragma unroll
        for (int tt = 0; tt < 8; tt++) {
            float lo, hi;
            UNPACK_F32X2(lo, hi, acc[tt]);
            zbc[(t0 + tt) * Vdim + i0] = lo;
            if (i0 + 1 < Vdim) zbc[(t0 + tt) * Vdim + i0 + 1] = hi;
        }
    }
}

// ---------------------------------------------------------------------------
// kC: conv3.  out[b,o,p] = sum_c W3[o,c]*z[b,c,p] + b3[o],  p in [0,TV)
// Block = (32-wide p tile, b). Thread = (o, psub): o fixed -> W3 row lives in
// 64 registers (loaded once); z tile (64c x 32p = 8KB) broadcast from smem.
// f32x2 pairs over adjacent p. Per c: 2 LDS.128 + 1 dup + 4 FFMA2.
// ---------------------------------------------------------------------------
__global__ __launch_bounds__(256) void kC(const float* __restrict__ W3,
                                          const float* __restrict__ b3,
                                          float* __restrict__ out) {
    const int b = blockIdx.y;
    const int p_base = blockIdx.x * 32;
    const int tid = threadIdx.x;
    const int o = tid >> 2;          // 0..63
    const int psub = tid & 3;        // 0..3  -> 8 p's each

    __shared__ __align__(16) float zs[Cdim * 32];   // 8 KB

    // W3 row for this thread's o -> registers (16 float4 LDG, L1/L2 resident)
    float w[Cdim];
    {
        const float4* wp = reinterpret_cast<const float4*>(W3 + o * Cdim);
#pragma unroll
        for (int q = 0; q < Cdim / 4; q++) {
            float4 f = wp[q];
            w[4 * q + 0] = f.x; w[4 * q + 1] = f.y;
            w[4 * q + 2] = f.z; w[4 * q + 3] = f.w;
        }
    }

    // stage z tile: zs[c][j] = z[b, c, p_base + j]
    const float* zb = g_z + (size_t)b * Cdim * TV + p_base;
    for (int idx = tid; idx < Cdim * 32; idx += 256) {
        int c = idx >> 5, j = idx & 31;
        zs[idx] = zb[(size_t)c * TV + j];
    }
    __syncthreads();

    unsigned long long acc[4];
#pragma unroll
    for (int q = 0; q < 4; q++) acc[q] = 0ull;

#pragma unroll 4
    for (int c = 0; c < Cdim; c++) {
        const float4* zp = reinterpret_cast<const float4*>(&zs[c * 32 + psub * 8]);
        float4 za = zp[0], zb4 = zp[1];
        unsigned long long zp0, zp1, zp2, zp3, wd;
        PACK_F32X2(zp0, za.x, za.y);
        PACK_F32X2(zp1, za.z, za.w);
        PACK_F32X2(zp2, zb4.x, zb4.y);
        PACK_F32X2(zp3, zb4.z, zb4.w);
        PACK_F32X2(wd, w[c], w[c]);
        FMA_F32X2(acc[0], zp0, wd);
        FMA_F32X2(acc[1], zp1, wd);
        FMA_F32X2(acc[2], zp2, wd);
        FMA_F32X2(acc[3], zp3, wd);
    }

    const float bo = b3[o];
    float r[8];
#pragma unroll
    for (int q = 0; q < 4; q++) {
        float lo, hi;
        UNPACK_F32X2(lo, hi, acc[q]);
        r[2 * q] = lo + bo;
        r[2 * q + 1] = hi + bo;
    }
    float* op = out + ((size_t)b * OUTdim + o) * TV + p_base + psub * 8;
    float4* op4 = reinterpret_cast<float4*>(op);
    op4[0] = make_float4(r[0], r[1], r[2], r[3]);
    op4[1] = make_float4(r[4], r[5], r[6], r[7]);
}

// ---------------------------------------------------------------------------
extern "C" void kernel_launch(void* const* d_in, const int* in_sizes, int n_in,
                              void* d_out, int out_size) {
    const float* x  = (const float*)d_in[0];
    const float* A  = (const float*)d_in[1];
    const float* W1 = (const float*)d_in[2];
    const float* b1 = (const float*)d_in[3];
    const float* W2 = (const float*)d_in[4];
    const float* b2 = (const float*)d_in[5];
    const float* W4 = (const float*)d_in[6];
    const float* b4 = (const float*)d_in[7];
    const float* W3 = (const float*)d_in[8];
    const float* b3 = (const float*)d_in[9];
    float* out = (float*)d_out;

    kA1<<<dim3(Cdim, Bdim), 128>>>(x);
    kA2<<<Bdim, 256>>>(W1, b1, W2, b2);
    kB<<<dim3(Cdim, Bdim), 224>>>(x, A, W4, b4);
    kC<<<dim3(TV / 32, Bdim), 256>>>(W3, b3, out);
}

// round 9
// speedup vs baseline: 1.3642x; 1.3642x over previous
#include <cuda_runtime.h>
#include <cuda_bf16.h>

#define Bdim 64
#define Cdim 64
#define Tdim 128
#define Vdim 25
#define Rdim 8
#define TSdim 9
#define OUTdim 64
#define VV (Vdim*Vdim)          // 625
#define TV (Tdim*Vdim)          // 3200
#define XSTR 136                // T + TS-1 = 136 padded row
#define WKSTR 26                // Wks row stride (25 + 1 pad for 8B-aligned pairs)
#define PTILE 256               // kC p-tile

// scratch (device globals: no runtime allocation allowed)
__device__ float g_m[Bdim * Cdim * Vdim];                 // 0.41 MB  (time-mean)
__device__ float g_rel[Bdim * Rdim * VV];                 // 1.28 MB
__device__ float g_z[(size_t)Bdim * Cdim * Tdim * Vdim];  // 52.4 MB

// ---- f32x2 helpers (sm_103a packed FFMA path) ------------------------------
#define PACK_F32X2(out, lo, hi)                                        \
    asm("mov.b64 %0, {%1, %2};"                                        \
        : "=l"(out) : "r"(__float_as_uint(lo)), "r"(__float_as_uint(hi)))

#define UNPACK_F32X2(lo, hi, in)                                       \
    do { unsigned _ulo, _uhi;                                          \
         asm("mov.b64 {%0, %1}, %2;" : "=r"(_ulo), "=r"(_uhi) : "l"(in)); \
         lo = __uint_as_float(_ulo); hi = __uint_as_float(_uhi); } while (0)

#define FMA_F32X2(acc, a, b)                                           \
    asm("fma.rn.f32x2 %0, %1, %2, %0;" : "+l"(acc) : "l"(a), "l"(b))

// ---------------------------------------------------------------------------
// kA1: coalesced time-mean.  One block per (b,c): stage the (T,V) plane in
// smem via float4, reduce over t.   m[b,c,v] = mean_t x[b,c,t,v]
// ---------------------------------------------------------------------------
__global__ __launch_bounds__(128) void kA1(const float* __restrict__ x) {
    const int c = blockIdx.x, b = blockIdx.y;
    const int tid = threadIdx.x;
    __shared__ __align__(16) float pl[Tdim * Vdim];   // 12.8 KB
    __shared__ float part[100];

    const float4* src = reinterpret_cast<const float4*>(
        x + ((size_t)b * Cdim + c) * TV);
    float4* dst = reinterpret_cast<float4*>(pl);
    for (int i = tid; i < TV / 4; i += 128) dst[i] = src[i];
    __syncthreads();

    if (tid < 100) {
        const int v = tid % Vdim, q = tid / Vdim;   // q = quarter of t-range
        float s = 0.f;
#pragma unroll 8
        for (int j = 0; j < 32; j++) s += pl[(q * 32 + j) * Vdim + v];
        part[tid] = s;
    }
    __syncthreads();
    if (tid < Vdim) {
        float s = part[tid] + part[25 + tid] + part[50 + tid] + part[75 + tid];
        g_m[((size_t)b * Cdim + c) * Vdim + tid] = s * (1.0f / Tdim);
    }
}

// ---------------------------------------------------------------------------
// kA2: per-batch projections + tanh relation (tiny).
// ---------------------------------------------------------------------------
__global__ __launch_bounds__(256) void kA2(const float* __restrict__ W1,
                                           const float* __restrict__ b1,
                                           const float* __restrict__ W2,
                                           const float* __restrict__ b2) {
    const int b = blockIdx.x;
    const int tid = threadIdx.x;
    __shared__ float W1s[Rdim * Cdim], W2s[Rdim * Cdim];
    __shared__ float ms[Cdim * Vdim];
    __shared__ float x1s[Rdim * Vdim], x2s[Rdim * Vdim];

    for (int i = tid; i < Rdim * Cdim; i += 256) {
        W1s[i] = W1[i];
        W2s[i] = W2[i];
    }
    const float* mb = g_m + (size_t)b * Cdim * Vdim;
    for (int i = tid; i < Cdim * Vdim; i += 256) ms[i] = mb[i];
    __syncthreads();

    for (int item = tid; item < 2 * Rdim * Vdim; item += 256) {
        int which = item / (Rdim * Vdim);
        int rv = item % (Rdim * Vdim);
        int r = rv / Vdim, v = rv % Vdim;
        const float* Ws = which ? W2s : W1s;
        float s = which ? b2[r] : b1[r];
#pragma unroll
        for (int c = 0; c < Cdim; c++) s += Ws[r * Cdim + c] * ms[c * Vdim + v];
        if (which) x2s[rv] = s; else x1s[rv] = s;
    }
    __syncthreads();

    float* relb = g_rel + (size_t)b * Rdim * VV;
    for (int item = tid; item < Rdim * VV; item += 256) {
        int r = item / VV;
        int rem = item % VV;
        int i = rem / Vdim, j = rem % Vdim;
        relb[item] = tanhf(x1s[r * Vdim + i] - x2s[r * Vdim + j]);
    }
}

// ---------------------------------------------------------------------------
// kB: per-(b,c) fused dynamic-tap conv, packed f32x2 over the i dimension.
//   Wk[k][v][i] = b4[c*TS+k] + A[v,i] + sum_r W4[c*TS+k,r]*rel[b,r,v,i]
//   z[t,i]      = sum_{v,k} xs[v][t+k] * Wk[k][v][i]
// Build phase restructured: item = vi, rel row loaded ONCE into registers,
// all 9 taps emitted (9x less L2 traffic than the k-major version).
// ---------------------------------------------------------------------------
__global__ __launch_bounds__(224) void kB(const float* __restrict__ x,
                                          const float* __restrict__ A,
                                          const float* __restrict__ W4,
                                          const float* __restrict__ b4) {
    const int c = blockIdx.x;
    const int b = blockIdx.y;
    const int tid = threadIdx.x;

    __shared__ __align__(16) float Wks[TSdim * Vdim * WKSTR]; // 23.4 KB
    __shared__ __align__(16) float xs[Vdim * XSTR];           // 13.6 KB
    __shared__ float W4s[TSdim * Rdim];                       // 72
    __shared__ float b4s[TSdim];

    if (tid < TSdim * Rdim) W4s[tid] = W4[(size_t)c * TSdim * Rdim + tid];
    if (tid < TSdim) b4s[tid] = b4[c * TSdim + tid];
    __syncthreads();

    // build Wk: one rel-row read per vi, all taps written
    const float* relb = g_rel + (size_t)b * Rdim * VV;
    for (int vi = tid; vi < VV; vi += 224) {
        float rv[Rdim];
#pragma unroll
        for (int r = 0; r < Rdim; r++) rv[r] = relb[r * VV + vi];
        const float a = A[vi];
        const int v = vi / Vdim, i = vi % Vdim;
        float* wout = &Wks[v * WKSTR + i];
#pragma unroll
        for (int k = 0; k < TSdim; k++) {
            float s = b4s[k] + a;
#pragma unroll
            for (int r = 0; r < Rdim; r++) s += W4s[k * Rdim + r] * rv[r];
            wout[(size_t)k * Vdim * WKSTR] = s;
        }
    }
    for (int item = tid; item < TSdim * Vdim; item += 224)
        Wks[item * WKSTR + Vdim] = 0.f;   // zero the pad column

    // stage x tile: xs[v][0..7] = 0 (causal pad), xs[v][8+t] = x[b,c,t,v]
    for (int i = tid; i < Vdim * 8; i += 224)
        xs[(i / 8) * XSTR + (i % 8)] = 0.f;
    const float* xbc = x + ((size_t)b * Cdim + c) * TV;
    for (int item = tid; item < TV; item += 224) {
        int t = item / Vdim, v = item % Vdim;
        xs[v * XSTR + 8 + t] = xbc[item];
    }
    __syncthreads();

    if (tid < 16 * 13) {
        const int tg = tid / 13;            // 0..15  -> t0 = 8*tg
        const int ip = tid % 13;            // 0..12  -> i0 = 2*ip
        const int i0 = 2 * ip;
        const int t0 = tg * 8;

        unsigned long long acc[8];
#pragma unroll
        for (int tt = 0; tt < 8; tt++) acc[tt] = 0ull;

#pragma unroll 1
        for (int v = 0; v < Vdim; v++) {
            float xv[16];
            const float4* xp4 = reinterpret_cast<const float4*>(&xs[v * XSTR + t0]);
#pragma unroll
            for (int q = 0; q < 4; q++) {
                float4 f = xp4[q];
                xv[4 * q + 0] = f.x; xv[4 * q + 1] = f.y;
                xv[4 * q + 2] = f.z; xv[4 * q + 3] = f.w;
            }
            unsigned long long xd[16];
#pragma unroll
            for (int j = 0; j < 16; j++) PACK_F32X2(xd[j], xv[j], xv[j]);

            const float* wkbase = &Wks[v * WKSTR + i0];
#pragma unroll
            for (int k = 0; k < TSdim; k++) {
                unsigned long long wp =
                    *reinterpret_cast<const unsigned long long*>(
                        wkbase + (size_t)k * Vdim * WKSTR);
#pragma unroll
                for (int tt = 0; tt < 8; tt++) FMA_F32X2(acc[tt], xd[tt + k], wp);
            }
        }

        float* zbc = g_z + ((size_t)b * Cdim + c) * TV;
#pragma unroll
        for (int tt = 0; tt < 8; tt++) {
            float lo, hi;
            UNPACK_F32X2(lo, hi, acc[tt]);
            zbc[(t0 + tt) * Vdim + i0] = lo;
            if (i0 + 1 < Vdim) zbc[(t0 + tt) * Vdim + i0 + 1] = hi;
        }
    }
}

// ---------------------------------------------------------------------------
// kC: conv3 as register-tiled GEMM.  out[b,o,p] = sum_c W3[o,c]*z[b,c,p]+b3[o]
// Block = (256-wide p tile, b), 256 threads. Thread = (og, pg) owns 8 o x 8 p
// (32 f32x2 accumulators paired over p). z tile + transposed W3 in dynamic
// smem (80 KB). Per c: 2 LDS.128 (z, pre-packed pairs) + 2 LDS.128 (w) +
// 8 dup movs + 32 FFMA2 -> FMA2-pipe bound, ~1 B/MAC of smem traffic.
// ---------------------------------------------------------------------------
__global__ __launch_bounds__(256) void kC(const float* __restrict__ W3,
                                          const float* __restrict__ b3,
                                          float* __restrict__ out) {
    extern __shared__ __align__(16) float smemC[];
    float* zs  = smemC;                  // [c][p]  64 x 256   (64 KB)
    float* w3t = smemC + Cdim * PTILE;   // [c][o]  64 x 64    (16 KB)

    const int b = blockIdx.y;
    const int p_base = blockIdx.x * PTILE;
    const int tid = threadIdx.x;
    const int og = tid >> 5;             // 0..7  -> o0 = og*8
    const int pg = tid & 31;             // 0..31 -> p0 = pg*8 (in tile)
    const int o0 = og * 8;
    const int pmax = TV - p_base;        // 256 (full) or 128 (last tile)

    // stage W3 transposed (coalesced read, smem scatter)
    for (int i = tid; i < Cdim * OUTdim; i += 256) {
        int o = i >> 6, c = i & 63;
        w3t[c * OUTdim + o] = W3[i];
    }
    // stage z tile (coalesced float4, zero-fill out-of-range)
    for (int i4 = tid; i4 < Cdim * (PTILE / 4); i4 += 256) {
        int c = i4 >> 6, j4 = i4 & 63;
        float4 v = make_float4(0.f, 0.f, 0.f, 0.f);
        if (j4 * 4 < pmax)
            v = *reinterpret_cast<const float4*>(
                g_z + ((size_t)b * Cdim + c) * TV + p_base + j4 * 4);
        *reinterpret_cast<float4*>(&zs[c * PTILE + j4 * 4]) = v;
    }
    __syncthreads();

    unsigned long long acc[8][4];
#pragma unroll
    for (int oo = 0; oo < 8; oo++)
#pragma unroll
        for (int q = 0; q < 4; q++) acc[oo][q] = 0ull;

#pragma unroll 2
    for (int c = 0; c < Cdim; c++) {
        const ulonglong2 za = *reinterpret_cast<const ulonglong2*>(&zs[c * PTILE + pg * 8]);
        const ulonglong2 zb2 = *reinterpret_cast<const ulonglong2*>(&zs[c * PTILE + pg * 8 + 4]);
        const float4 wa = *reinterpret_cast<const float4*>(&w3t[c * OUTdim + o0]);
        const float4 wb = *reinterpret_cast<const float4*>(&w3t[c * OUTdim + o0 + 4]);
        float wf[8] = {wa.x, wa.y, wa.z, wa.w, wb.x, wb.y, wb.z, wb.w};
        unsigned long long wd[8];
#pragma unroll
        for (int oo = 0; oo < 8; oo++) PACK_F32X2(wd[oo], wf[oo], wf[oo]);
#pragma unroll
        for (int oo = 0; oo < 8; oo++) {
            FMA_F32X2(acc[oo][0], za.x,  wd[oo]);
            FMA_F32X2(acc[oo][1], za.y,  wd[oo]);
            FMA_F32X2(acc[oo][2], zb2.x, wd[oo]);
            FMA_F32X2(acc[oo][3], zb2.y, wd[oo]);
        }
    }

    // epilogue: add bias, write 8 o-rows x 8 p (p-block fully valid or fully out)
    if (pg * 8 < pmax) {
#pragma unroll
        for (int oo = 0; oo < 8; oo++) {
            const float bo = b3[o0 + oo];
            float r[8];
#pragma unroll
            for (int q = 0; q < 4; q++) {
                float lo, hi;
                UNPACK_F32X2(lo, hi, acc[oo][q]);
                r[2 * q] = lo + bo;
                r[2 * q + 1] = hi + bo;
            }
            float4* op4 = reinterpret_cast<float4*>(
                out + ((size_t)b * OUTdim + o0 + oo) * TV + p_base + pg * 8);
            op4[0] = make_float4(r[0], r[1], r[2], r[3]);
            op4[1] = make_float4(r[4], r[5], r[6], r[7]);
        }
    }
}

// ---------------------------------------------------------------------------
extern "C" void kernel_launch(void* const* d_in, const int* in_sizes, int n_in,
                              void* d_out, int out_size) {
    const float* x  = (const float*)d_in[0];
    const float* A  = (const float*)d_in[1];
    const float* W1 = (const float*)d_in[2];
    const float* b1 = (const float*)d_in[3];
    const float* W2 = (const float*)d_in[4];
    const float* b2 = (const float*)d_in[5];
    const float* W4 = (const float*)d_in[6];
    const float* b4 = (const float*)d_in[7];
    const float* W3 = (const float*)d_in[8];
    const float* b3 = (const float*)d_in[9];
    float* out = (float*)d_out;

    const int kc_smem = (Cdim * PTILE + Cdim * OUTdim) * (int)sizeof(float); // 80 KB
    cudaFuncSetAttribute(kC, cudaFuncAttributeMaxDynamicSharedMemorySize, kc_smem);

    kA1<<<dim3(Cdim, Bdim), 128>>>(x);
    kA2<<<Bdim, 256>>>(W1, b1, W2, b2);
    kB<<<dim3(Cdim, Bdim), 224>>>(x, A, W4, b4);
    kC<<<dim3((TV + PTILE - 1) / PTILE, Bdim), 256, kc_smem>>>(W3, b3, out);
}